// round 9
// baseline (speedup 1.0000x reference)
#include <cuda_runtime.h>
#include <cuda_fp16.h>
#include <math.h>

#define N_NODES   50000
#define N_GRAPHS  64
#define IN_DIM    128
#define HID       64
#define H1        8
#define D1        (H1*HID)          /* 512 */
#define E_MAX     800000
#define ET_MAX    (E_MAX + N_NODES) /* edges + self loops */
#define NEG_SLOPE 0.2f

// ---------------- scratch (static device arrays; no allocation) ----------------
__device__ __half g_h1 [N_NODES * D1];    // x @ W1 (fp16)
__device__ __half g_o1 [N_NODES * D1];    // relu(gat1) (fp16)
__device__ __half g_h2 [N_NODES * HID];   // o1 @ W2 (fp16)
__device__ float g_as1[N_NODES * H1];     // [node][head]
__device__ float g_ad1[N_NODES * H1];
__device__ float g_as2[N_NODES];
__device__ float g_ad2[N_NODES];
__device__ float g_w1 [ET_MAX * H1];      // per-(edge,head) exp weights
__device__ float g_w2 [ET_MAX];
__device__ int   g_csr[ET_MAX];           // src ids grouped by dst
__device__ int   g_dst[ET_MAX];           // dst ids (same order)
__device__ int   g_off[N_NODES + 1];
__device__ int   g_cnt[N_NODES];          // histogram, then scatter cursor
__device__ float g_pool[N_GRAPHS * HID];

struct h2x4 { __half2 a, b, c, d; };      // 16-byte fp16 vector store

// ---------------- zero all accumulators ----------------
__global__ void zero_k(int N) {
    int i = blockIdx.x * blockDim.x + threadIdx.x;
    if (i < N * H1) { g_as1[i] = 0.f; g_ad1[i] = 0.f; }
    if (i < N)      { g_cnt[i] = 0;   g_as2[i] = 0.f; g_ad2[i] = 0.f; }
    if (i < N_GRAPHS * HID) g_pool[i] = 0.f;
}

__global__ void hist_k(const int* __restrict__ ei, int E) {
    int i = blockIdx.x * blockDim.x + threadIdx.x;
    if (i < E) atomicAdd(&g_cnt[ei[E + i]], 1);   // dst
}

// single-block scan of (cnt[i] + 1) -> exclusive offsets; also seeds cursor
__global__ void scan_k(int n) {
    __shared__ int part[1024];
    int t = threadIdx.x;
    int ch = (n + 1023) / 1024;
    int b = t * ch, e = min(b + ch, n);
    int s = 0;
    for (int i = b; i < e; i++) s += g_cnt[i] + 1;
    part[t] = s;
    __syncthreads();
    for (int off = 1; off < 1024; off <<= 1) {
        int v = (t >= off) ? part[t - off] : 0;
        __syncthreads();
        part[t] += v;
        __syncthreads();
    }
    int base = (t == 0) ? 0 : part[t - 1];
    for (int i = b; i < e; i++) {
        int c = g_cnt[i];
        g_off[i] = base;
        g_cnt[i] = base;          // cursor for scatter
        base += c + 1;            // +1 reserves self-loop slot
    }
    if (t == 1023) g_off[n] = part[1023];
}

// scatter edges (+dst ids) + fill reserved self-loop slots
__global__ void scatter_self_k(const int* __restrict__ ei, int E, int N) {
    int i = blockIdx.x * blockDim.x + threadIdx.x;
    if (i < E) {
        int s = ei[i], d = ei[E + i];
        int pos = atomicAdd(&g_cnt[d], 1);
        g_csr[pos] = s;
        g_dst[pos] = d;
    } else {
        int n = i - E;
        if (n < N) {
            int slot = g_off[n + 1] - 1;
            g_csr[slot] = n;
            g_dst[slot] = n;
        }
    }
}

// ---------------- edge-weight precompute ----------------
__global__ void wk1_k(int tot) {
    int i = blockIdx.x * blockDim.x + threadIdx.x;
    if (i >= tot * H1) return;
    int e = i >> 3, h = i & 7;
    int s = g_csr[e], d = g_dst[e];
    float v = g_as1[s * 8 + h] + g_ad1[d * 8 + h];
    v = v > 0.f ? v : NEG_SLOPE * v;
    g_w1[i] = __expf(v);
}

__global__ void wk2_k(int tot) {
    int e = blockIdx.x * blockDim.x + threadIdx.x;
    if (e >= tot) return;
    float v = g_as2[g_csr[e]] + g_ad2[g_dst[e]];
    v = v > 0.f ? v : NEG_SLOPE * v;
    g_w2[e] = __expf(v);
}

// ---------------- fp16 tensor-core GEMM + fused alpha epilogue ----------------
__device__ __forceinline__ unsigned pkh2(float a, float b) {
    __half2 h = __floats2half2_rn(a, b);
    return *reinterpret_cast<unsigned*>(&h);
}
__device__ __forceinline__ void ldA16(const float* p, uint4& x, uint4& y) {
    float4 f0 = *(const float4*)p,       f1 = *(const float4*)(p + 4);
    float4 f2 = *(const float4*)(p + 8), f3 = *(const float4*)(p + 12);
    x = make_uint4(pkh2(f0.x, f0.y), pkh2(f0.z, f0.w), pkh2(f1.x, f1.y), pkh2(f1.z, f1.w));
    y = make_uint4(pkh2(f2.x, f2.y), pkh2(f2.z, f2.w), pkh2(f3.x, f3.y), pkh2(f3.z, f3.w));
}
__device__ __forceinline__ void ldA16(const __half* p, uint4& x, uint4& y) {
    x = *(const uint4*)p;
    y = *(const uint4*)(p + 8);
}
__device__ __forceinline__ void st2(float* p, float a, float b) {
    *(float2*)p = make_float2(a, b);
}
__device__ __forceinline__ void st2(__half* p, float a, float b) {
    *(__half2*)p = __floats2half2_rn(a, b);
}

// C[M,N] = A[M,K] x B[K,N] via mma.sync m16n8k16 fp16, fp32 accumulate.
// Register-double-buffered: chunk k+1 fetched (and fp16-converted) while chunk k
// is consumed by the MMAs -> global latency hidden under tensor work.
// Fused: as_out[m*H + col/64] += sum_c C[m,c]*avs[c] (atomicAdd partials; pre-zeroed)
// BM=128, BK=32, 256 threads (8 warps, 2x4). BN=128 (gemm1) / 64 (gemm2).
template<int BN, int H, typename TA, typename TC>
__global__ __launch_bounds__(256, 2) void mma_ep(
    const TA* __restrict__ A, const float* __restrict__ B, TC* __restrict__ C,
    const float* __restrict__ avs, const float* __restrict__ avd,
    float* __restrict__ as_out, float* __restrict__ ad_out,
    int M, int N, int K)
{
    constexpr int BM = 128, BK = 32;
    constexpr int MT = 4, NT = BN / 32;   // warp tile: 64 x (BN/4)
    constexpr int WCOLS = BN / 4;
    constexpr int RS = 20;                // u32 words per row (16 data + 4 pad)
    constexpr int KE = BK * BN / 256;     // B k-elements per thread (16 or 8)
    __shared__ unsigned As[BM * RS];      // [row][k/2] half2 words
    __shared__ unsigned Bs[BN * RS];      // [n][k/2]   half2 words

    int t = threadIdx.x, lane = t & 31;
    int wid = t >> 5, wm = wid >> 2, wn = wid & 3;
    int lq = lane >> 2, lp = lane & 3;
    int m0 = blockIdx.x * BM, n0 = blockIdx.y * BN;

    float acc[MT][NT][4];
#pragma unroll
    for (int mt = 0; mt < MT; mt++)
#pragma unroll
        for (int nt = 0; nt < NT; nt++)
#pragma unroll
            for (int v = 0; v < 4; v++) acc[mt][nt][v] = 0.f;

    int ar = t >> 1, acb = (t & 1) * 16;
    bool aok = (m0 + ar) < M;
    const TA* Ap = A + (size_t)(m0 + ar) * K + acb;
    int bn = t % BN, bkb = (t / BN) * KE;
    const float* Bp = B + n0 + bn;

    uint4 ax = make_uint4(0,0,0,0), ay = make_uint4(0,0,0,0);
    unsigned bt[KE / 2];
    // prologue fetch (chunk 0)
    if (aok) ldA16(Ap, ax, ay);
#pragma unroll
    for (int j = 0; j < KE / 2; j++) {
        float v0 = Bp[(size_t)(bkb + 2 * j) * N];
        float v1 = Bp[(size_t)(bkb + 2 * j + 1) * N];
        bt[j] = pkh2(v0, v1);
    }

    for (int k0 = 0; k0 < K; k0 += BK) {
        // commit current chunk to smem
        uint4* adst = (uint4*)&As[ar * RS + (acb >> 1)];
        adst[0] = ax; adst[1] = ay;
        uint4* bdst = (uint4*)&Bs[bn * RS + (bkb >> 1)];
#pragma unroll
        for (int j = 0; j < KE / 2; j += 4)
            bdst[j >> 2] = make_uint4(bt[j], bt[j+1], bt[j+2], bt[j+3]);
        __syncthreads();
        // fetch next chunk into registers (overlaps the MMAs below)
        int kn = k0 + BK;
        if (kn < K) {
            ax = make_uint4(0,0,0,0); ay = make_uint4(0,0,0,0);
            if (aok) ldA16(Ap + kn, ax, ay);
#pragma unroll
            for (int j = 0; j < KE / 2; j++) {
                float v0 = Bp[(size_t)(kn + bkb + 2 * j) * N];
                float v1 = Bp[(size_t)(kn + bkb + 2 * j + 1) * N];
                bt[j] = pkh2(v0, v1);
            }
        }
#pragma unroll
        for (int ks = 0; ks < BK / 16; ks++) {
            unsigned a0[MT], a1[MT], a2[MT], a3[MT];
#pragma unroll
            for (int mt = 0; mt < MT; mt++) {
                int r = wm * 64 + mt * 16 + lq;
                const unsigned* pl = &As[r * RS + ks * 8 + lp];
                const unsigned* ph = &As[(r + 8) * RS + ks * 8 + lp];
                a0[mt] = pl[0]; a2[mt] = pl[4];
                a1[mt] = ph[0]; a3[mt] = ph[4];
            }
            unsigned b0[NT], b1[NT];
#pragma unroll
            for (int nt = 0; nt < NT; nt++) {
                const unsigned* pb = &Bs[(wn * WCOLS + nt * 8 + lq) * RS + ks * 8 + lp];
                b0[nt] = pb[0]; b1[nt] = pb[4];
            }
#pragma unroll
            for (int mt = 0; mt < MT; mt++)
#pragma unroll
                for (int nt = 0; nt < NT; nt++)
                    asm volatile(
                        "mma.sync.aligned.m16n8k16.row.col.f32.f16.f16.f32 "
                        "{%0,%1,%2,%3}, {%4,%5,%6,%7}, {%8,%9}, {%0,%1,%2,%3};"
                        : "+f"(acc[mt][nt][0]), "+f"(acc[mt][nt][1]),
                          "+f"(acc[mt][nt][2]), "+f"(acc[mt][nt][3])
                        : "r"(a0[mt]), "r"(a1[mt]), "r"(a2[mt]), "r"(a3[mt]),
                          "r"(b0[nt]), "r"(b1[nt]));
        }
        __syncthreads();
    }

    // store C + fused alpha partial dot products
    float ps[2][MT], pd[2][MT];
#pragma unroll
    for (int mt = 0; mt < MT; mt++) { ps[0][mt]=ps[1][mt]=pd[0][mt]=pd[1][mt]=0.f; }
#pragma unroll
    for (int mt = 0; mt < MT; mt++) {
        int r = m0 + wm * 64 + mt * 16 + lq;
#pragma unroll
        for (int nt = 0; nt < NT; nt++) {
            int c = n0 + wn * WCOLS + nt * 8 + 2 * lp;
            float s0 = avs[c], s1 = avs[c + 1];
            float d0 = avd[c], d1 = avd[c + 1];
            float* a = acc[mt][nt];
            if (r < M)     st2(C + (size_t)r * N + c,       a[0], a[1]);
            if (r + 8 < M) st2(C + (size_t)(r + 8) * N + c, a[2], a[3]);
            ps[0][mt] += a[0]*s0 + a[1]*s1;  ps[1][mt] += a[2]*s0 + a[3]*s1;
            pd[0][mt] += a[0]*d0 + a[1]*d1;  pd[1][mt] += a[2]*d0 + a[3]*d1;
        }
    }
#pragma unroll
    for (int o = 1; o <= 2; o <<= 1)
#pragma unroll
        for (int mt = 0; mt < MT; mt++) {
            ps[0][mt] += __shfl_xor_sync(0xffffffffu, ps[0][mt], o);
            ps[1][mt] += __shfl_xor_sync(0xffffffffu, ps[1][mt], o);
            pd[0][mt] += __shfl_xor_sync(0xffffffffu, pd[0][mt], o);
            pd[1][mt] += __shfl_xor_sync(0xffffffffu, pd[1][mt], o);
        }
    if (lp == 0) {
        int head = (n0 + wn * WCOLS) / 64;
#pragma unroll
        for (int mt = 0; mt < MT; mt++) {
            int r = m0 + wm * 64 + mt * 16 + lq;
            if (r < M) {
                atomicAdd(&as_out[r * H + head], ps[0][mt]);
                atomicAdd(&ad_out[r * H + head], pd[0][mt]);
            }
            if (r + 8 < M) {
                atomicAdd(&as_out[(r + 8) * H + head], ps[1][mt]);
                atomicAdd(&ad_out[(r + 8) * H + head], pd[1][mt]);
            }
        }
    }
}

// ---------------- GAT layer 1 aggregation ----------------
// 2 warps per node, each owns 256 cols; lane owns 8 fp16 cols (one LDG.128/edge).
// Full distance-1 prefetch: next group's (csr,w) AND features load while the
// current group's FMA/cvt execute.
__global__ __launch_bounds__(256) void gat1_k(
    const __half* __restrict__ feat, const float* __restrict__ w1,
    const float* __restrict__ bias, __half* __restrict__ out, int N)
{
    int warp = threadIdx.x >> 5, lane = threadIdx.x & 31;
    int node = blockIdx.x * 4 + (warp >> 1);
    int halfid = warp & 1;
    if (node >= N) return;
    int beg = g_off[node], end = g_off[node + 1];

    int col0 = halfid * 256 + lane * 8;
    int myh  = col0 >> 6;
    const __half* fb = feat + col0;

    float acc[8] = {0,0,0,0,0,0,0,0};
    float wsum = 0.f;

    float cw[4]; uint4 cf[4];
#pragma unroll
    for (int u = 0; u < 4; u++) {
        int e = beg + u; bool ok = e < end; e = ok ? e : end - 1;
        int s = g_csr[e];
        cw[u] = ok ? w1[e * 8 + myh] : 0.f;
        cf[u] = *(const uint4*)(fb + (size_t)s * D1);
    }
    for (int i = beg; i < end; i += 4) {
        float nw[4] = {0,0,0,0}; uint4 nf[4];
        int nb = i + 4;
        if (nb < end) {
#pragma unroll
            for (int u = 0; u < 4; u++) {
                int e = nb + u; bool ok = e < end; e = ok ? e : end - 1;
                int s = g_csr[e];
                nw[u] = ok ? w1[e * 8 + myh] : 0.f;
                nf[u] = *(const uint4*)(fb + (size_t)s * D1);
            }
        } else {
#pragma unroll
            for (int u = 0; u < 4; u++) nf[u] = make_uint4(0,0,0,0);
        }
#pragma unroll
        for (int u = 0; u < 4; u++) {
            float w = cw[u];
            wsum += w;
            float2 f0 = __half22float2(*reinterpret_cast<__half2*>(&cf[u].x));
            float2 f1 = __half22float2(*reinterpret_cast<__half2*>(&cf[u].y));
            float2 f2 = __half22float2(*reinterpret_cast<__half2*>(&cf[u].z));
            float2 f3 = __half22float2(*reinterpret_cast<__half2*>(&cf[u].w));
            acc[0] += w * f0.x; acc[1] += w * f0.y;
            acc[2] += w * f1.x; acc[3] += w * f1.y;
            acc[4] += w * f2.x; acc[5] += w * f2.y;
            acc[6] += w * f3.x; acc[7] += w * f3.y;
        }
#pragma unroll
        for (int u = 0; u < 4; u++) { cw[u] = nw[u]; cf[u] = nf[u]; }
    }
    float inv = 1.f / wsum;
    const float4* bp = (const float4*)(bias + col0);
    float4 b0 = bp[0], b1 = bp[1];
    h2x4 pack;
    pack.a = __floats2half2_rn(fmaxf(acc[0]*inv + b0.x, 0.f), fmaxf(acc[1]*inv + b0.y, 0.f));
    pack.b = __floats2half2_rn(fmaxf(acc[2]*inv + b0.z, 0.f), fmaxf(acc[3]*inv + b0.w, 0.f));
    pack.c = __floats2half2_rn(fmaxf(acc[4]*inv + b1.x, 0.f), fmaxf(acc[5]*inv + b1.y, 0.f));
    pack.d = __floats2half2_rn(fmaxf(acc[6]*inv + b1.z, 0.f), fmaxf(acc[7]*inv + b1.w, 0.f));
    *(h2x4*)(out + (size_t)node * D1 + col0) = pack;
}

// ---------------- GAT layer 2 fused with ReLU + global_add_pool ----------------
__global__ __launch_bounds__(256) void gat2_k(
    const __half* __restrict__ feat, const float* __restrict__ w2,
    const float* __restrict__ bias, const int* __restrict__ batch, int N)
{
    int warp = threadIdx.x >> 5, lane = threadIdx.x & 31;
    int node = blockIdx.x * 8 + warp;
    if (node >= N) return;
    int beg = g_off[node], end = g_off[node + 1];

    float2 acc = make_float2(0.f, 0.f);
    float wsum = 0.f;
    const __half* fb = feat + lane * 2;

    float cw[4]; __half2 cf[4];
#pragma unroll
    for (int u = 0; u < 4; u++) {
        int e = beg + u; bool ok = e < end; e = ok ? e : end - 1;
        int s = g_csr[e];
        cw[u] = ok ? w2[e] : 0.f;
        cf[u] = *(const __half2*)(fb + (size_t)s * HID);
    }
    for (int i = beg; i < end; i += 4) {
        float nw[4] = {0,0,0,0}; __half2 nf[4];
        int nb = i + 4;
        if (nb < end) {
#pragma unroll
            for (int u = 0; u < 4; u++) {
                int e = nb + u; bool ok = e < end; e = ok ? e : end - 1;
                int s = g_csr[e];
                nw[u] = ok ? w2[e] : 0.f;
                nf[u] = *(const __half2*)(fb + (size_t)s * HID);
            }
        } else {
#pragma unroll
            for (int u = 0; u < 4; u++) nf[u] = __floats2half2_rn(0.f, 0.f);
        }
#pragma unroll
        for (int u = 0; u < 4; u++) {
            float w = cw[u];
            wsum += w;
            float2 f = __half22float2(cf[u]);
            acc.x += w * f.x;
            acc.y += w * f.y;
        }
#pragma unroll
        for (int u = 0; u < 4; u++) { cw[u] = nw[u]; cf[u] = nf[u]; }
    }
    float inv = 1.f / wsum;
    int col = lane * 2;
    float v0 = fmaxf(acc.x * inv + bias[col],     0.f);
    float v1 = fmaxf(acc.y * inv + bias[col + 1], 0.f);
    int g = batch[node];
    atomicAdd(&g_pool[g * HID + col],     v0);
    atomicAdd(&g_pool[g * HID + col + 1], v1);
}

// ---------------- FC ----------------
__global__ void fc_k(const float* __restrict__ W, const float* __restrict__ b,
                     float* __restrict__ out)
{
    int t = threadIdx.x;
    if (t >= N_GRAPHS * 10) return;
    int g = t / 10, o = t % 10;
    float s = b[o];
#pragma unroll
    for (int c = 0; c < HID; c++) s += g_pool[g * HID + c] * W[c * 10 + o];
    out[t] = s;
}

// ---------------- host ----------------
extern "C" void kernel_launch(void* const* d_in, const int* in_sizes, int n_in,
                              void* d_out, int out_size)
{
    const float* x      = (const float*)d_in[0];
    const int*   ei     = (const int*)  d_in[1];
    const int*   batch  = (const int*)  d_in[2];
    const float* W1     = (const float*)d_in[3];
    const float* a_src1 = (const float*)d_in[4];
    const float* a_dst1 = (const float*)d_in[5];
    const float* b1     = (const float*)d_in[6];
    const float* W2     = (const float*)d_in[7];
    const float* a_src2 = (const float*)d_in[8];
    const float* a_dst2 = (const float*)d_in[9];
    const float* b2     = (const float*)d_in[10];
    const float* W_fc   = (const float*)d_in[11];
    const float* b_fc   = (const float*)d_in[12];

    int N = in_sizes[0] / IN_DIM;      // 50000
    int E = in_sizes[1] / 2;           // 800000
    int ET = E + N;

    __half *h1, *o1, *h2;
    float *as1, *ad1, *as2, *ad2, *w1b, *w2b;
    cudaGetSymbolAddress((void**)&h1,  g_h1);
    cudaGetSymbolAddress((void**)&o1,  g_o1);
    cudaGetSymbolAddress((void**)&h2,  g_h2);
    cudaGetSymbolAddress((void**)&as1, g_as1);
    cudaGetSymbolAddress((void**)&ad1, g_ad1);
    cudaGetSymbolAddress((void**)&as2, g_as2);
    cudaGetSymbolAddress((void**)&ad2, g_ad2);
    cudaGetSymbolAddress((void**)&w1b, g_w1);
    cudaGetSymbolAddress((void**)&w2b, g_w2);

    // 1..3: zero + degree histogram + offsets
    zero_k<<<(N * H1 + 255) / 256, 256>>>(N);
    hist_k<<<(E + 255) / 256, 256>>>(ei, E);
    scan_k<<<1, 1024>>>(N);
    // 4: fp16 GEMM1 + alpha epilogue (profiled slot)
    mma_ep<128, H1><<<dim3((N + 127) / 128, D1 / 128), 256>>>(
        x, W1, h1, a_src1, a_dst1, as1, ad1, N, D1, IN_DIM);
    // 5: CSR scatter (+dst) + self-loops
    scatter_self_k<<<(E + N + 255) / 256, 256>>>(ei, E, N);
    // 6: edge weights layer 1
    wk1_k<<<(ET * H1 + 255) / 256, 256>>>(ET);
    // 7: GAT layer 1 aggregation
    gat1_k<<<(N + 3) / 4, 256>>>(h1, w1b, b1, o1, N);
    // 8: fp16 GEMM2 + alpha epilogue (A fp16)
    mma_ep<64, 1><<<dim3((N + 127) / 128, 1), 256>>>(
        o1, W2, h2, a_src2, a_dst2, as2, ad2, N, HID, D1);
    // 9: edge weights layer 2
    wk2_k<<<(ET + 255) / 256, 256>>>(ET);
    // 10: GAT layer 2 fused with ReLU + pool
    gat2_k<<<(N + 7) / 8, 256>>>(h2, w2b, b2, batch, N);
    // 11: FC
    fc_k<<<1, 640>>>(W_fc, b_fc, (float*)d_out);
}

// round 10
// speedup vs baseline: 1.0228x; 1.0228x over previous
#include <cuda_runtime.h>
#include <cuda_fp16.h>
#include <math.h>

#define N_NODES   50000
#define N_GRAPHS  64
#define IN_DIM    128
#define HID       64
#define H1        8
#define D1        (H1*HID)          /* 512 */
#define E_MAX     800000
#define ET_MAX    (E_MAX + N_NODES) /* edges + self loops */
#define NEG_SLOPE 0.2f

// ---------------- scratch (static device arrays; no allocation) ----------------
__device__ __half g_h1 [N_NODES * D1];    // x @ W1 (fp16)
__device__ __half g_o1 [N_NODES * D1];    // relu(gat1) (fp16)
__device__ __half g_h2 [N_NODES * HID];   // o1 @ W2 (fp16)
__device__ float g_as1[N_NODES * H1];     // [node][head]
__device__ float g_ad1[N_NODES * H1];
__device__ float g_as2[N_NODES];
__device__ float g_ad2[N_NODES];
__device__ float g_w1 [ET_MAX * H1];      // per-(edge,head) exp weights
__device__ int   g_csr[ET_MAX];           // src ids grouped by dst
__device__ int   g_dst[ET_MAX];           // dst ids (same order)
__device__ int   g_off[N_NODES + 1];
__device__ int   g_cnt[N_NODES];          // histogram, then scatter cursor
__device__ float g_pool[N_GRAPHS * HID];

struct h2x4 { __half2 a, b, c, d; };      // 16-byte fp16 vector store

// ---------------- zero all accumulators ----------------
__global__ void zero_k(int N) {
    int i = blockIdx.x * blockDim.x + threadIdx.x;
    if (i < N * H1) { g_as1[i] = 0.f; g_ad1[i] = 0.f; }
    if (i < N)      { g_cnt[i] = 0;   g_as2[i] = 0.f; g_ad2[i] = 0.f; }
    if (i < N_GRAPHS * HID) g_pool[i] = 0.f;
}

__global__ void hist_k(const int* __restrict__ ei, int E) {
    int i = blockIdx.x * blockDim.x + threadIdx.x;
    if (i < E) atomicAdd(&g_cnt[ei[E + i]], 1);   // dst
}

// single-block scan of (cnt[i] + 1) -> exclusive offsets; also seeds cursor
__global__ void scan_k(int n) {
    __shared__ int part[1024];
    int t = threadIdx.x;
    int ch = (n + 1023) / 1024;
    int b = t * ch, e = min(b + ch, n);
    int s = 0;
    for (int i = b; i < e; i++) s += g_cnt[i] + 1;
    part[t] = s;
    __syncthreads();
    for (int off = 1; off < 1024; off <<= 1) {
        int v = (t >= off) ? part[t - off] : 0;
        __syncthreads();
        part[t] += v;
        __syncthreads();
    }
    int base = (t == 0) ? 0 : part[t - 1];
    for (int i = b; i < e; i++) {
        int c = g_cnt[i];
        g_off[i] = base;
        g_cnt[i] = base;          // cursor for scatter
        base += c + 1;            // +1 reserves self-loop slot
    }
    if (t == 1023) g_off[n] = part[1023];
}

// scatter edges (+dst ids) + fill reserved self-loop slots
__global__ void scatter_self_k(const int* __restrict__ ei, int E, int N) {
    int i = blockIdx.x * blockDim.x + threadIdx.x;
    if (i < E) {
        int s = ei[i], d = ei[E + i];
        int pos = atomicAdd(&g_cnt[d], 1);
        g_csr[pos] = s;
        g_dst[pos] = d;
    } else {
        int n = i - E;
        if (n < N) {
            int slot = g_off[n + 1] - 1;
            g_csr[slot] = n;
            g_dst[slot] = n;
        }
    }
}

// ---------------- edge-weight precompute (layer 1) ----------------
__global__ void wk1_k(int tot) {
    int i = blockIdx.x * blockDim.x + threadIdx.x;
    if (i >= tot * H1) return;
    int e = i >> 3, h = i & 7;
    int s = g_csr[e], d = g_dst[e];
    float v = g_as1[s * 8 + h] + g_ad1[d * 8 + h];
    v = v > 0.f ? v : NEG_SLOPE * v;
    g_w1[i] = __expf(v);
}

// ---------------- fp16 tensor-core GEMM + fused alpha epilogue ----------------
__device__ __forceinline__ unsigned pkh2(float a, float b) {
    __half2 h = __floats2half2_rn(a, b);
    return *reinterpret_cast<unsigned*>(&h);
}
__device__ __forceinline__ void ldA16(const float* p, uint4& x, uint4& y) {
    float4 f0 = *(const float4*)p,       f1 = *(const float4*)(p + 4);
    float4 f2 = *(const float4*)(p + 8), f3 = *(const float4*)(p + 12);
    x = make_uint4(pkh2(f0.x, f0.y), pkh2(f0.z, f0.w), pkh2(f1.x, f1.y), pkh2(f1.z, f1.w));
    y = make_uint4(pkh2(f2.x, f2.y), pkh2(f2.z, f2.w), pkh2(f3.x, f3.y), pkh2(f3.z, f3.w));
}
__device__ __forceinline__ void ldA16(const __half* p, uint4& x, uint4& y) {
    x = *(const uint4*)p;
    y = *(const uint4*)(p + 8);
}
__device__ __forceinline__ void st2(float* p, float a, float b) {
    *(float2*)p = make_float2(a, b);
}
__device__ __forceinline__ void st2(__half* p, float a, float b) {
    *(__half2*)p = __floats2half2_rn(a, b);
}

// C[M,N] = A[M,K] x B[K,N] via mma.sync m16n8k16 fp16, fp32 accumulate.
// Register-double-buffered. Fused alpha epilogue (atomicAdd partials; pre-zeroed).
template<int BN, int H, typename TA, typename TC>
__global__ __launch_bounds__(256, 2) void mma_ep(
    const TA* __restrict__ A, const float* __restrict__ B, TC* __restrict__ C,
    const float* __restrict__ avs, const float* __restrict__ avd,
    float* __restrict__ as_out, float* __restrict__ ad_out,
    int M, int N, int K)
{
    constexpr int BM = 128, BK = 32;
    constexpr int MT = 4, NT = BN / 32;   // warp tile: 64 x (BN/4)
    constexpr int WCOLS = BN / 4;
    constexpr int RS = 20;                // u32 words per row (16 data + 4 pad)
    constexpr int KE = BK * BN / 256;     // B k-elements per thread (16 or 8)
    __shared__ unsigned As[BM * RS];      // [row][k/2] half2 words
    __shared__ unsigned Bs[BN * RS];      // [n][k/2]   half2 words

    int t = threadIdx.x, lane = t & 31;
    int wid = t >> 5, wm = wid >> 2, wn = wid & 3;
    int lq = lane >> 2, lp = lane & 3;
    int m0 = blockIdx.x * BM, n0 = blockIdx.y * BN;

    float acc[MT][NT][4];
#pragma unroll
    for (int mt = 0; mt < MT; mt++)
#pragma unroll
        for (int nt = 0; nt < NT; nt++)
#pragma unroll
            for (int v = 0; v < 4; v++) acc[mt][nt][v] = 0.f;

    int ar = t >> 1, acb = (t & 1) * 16;
    bool aok = (m0 + ar) < M;
    const TA* Ap = A + (size_t)(m0 + ar) * K + acb;
    int bn = t % BN, bkb = (t / BN) * KE;
    const float* Bp = B + n0 + bn;

    uint4 ax = make_uint4(0,0,0,0), ay = make_uint4(0,0,0,0);
    unsigned bt[KE / 2];
    if (aok) ldA16(Ap, ax, ay);
#pragma unroll
    for (int j = 0; j < KE / 2; j++) {
        float v0 = Bp[(size_t)(bkb + 2 * j) * N];
        float v1 = Bp[(size_t)(bkb + 2 * j + 1) * N];
        bt[j] = pkh2(v0, v1);
    }

    for (int k0 = 0; k0 < K; k0 += BK) {
        uint4* adst = (uint4*)&As[ar * RS + (acb >> 1)];
        adst[0] = ax; adst[1] = ay;
        uint4* bdst = (uint4*)&Bs[bn * RS + (bkb >> 1)];
#pragma unroll
        for (int j = 0; j < KE / 2; j += 4)
            bdst[j >> 2] = make_uint4(bt[j], bt[j+1], bt[j+2], bt[j+3]);
        __syncthreads();
        int kn = k0 + BK;
        if (kn < K) {
            ax = make_uint4(0,0,0,0); ay = make_uint4(0,0,0,0);
            if (aok) ldA16(Ap + kn, ax, ay);
#pragma unroll
            for (int j = 0; j < KE / 2; j++) {
                float v0 = Bp[(size_t)(kn + bkb + 2 * j) * N];
                float v1 = Bp[(size_t)(kn + bkb + 2 * j + 1) * N];
                bt[j] = pkh2(v0, v1);
            }
        }
#pragma unroll
        for (int ks = 0; ks < BK / 16; ks++) {
            unsigned a0[MT], a1[MT], a2[MT], a3[MT];
#pragma unroll
            for (int mt = 0; mt < MT; mt++) {
                int r = wm * 64 + mt * 16 + lq;
                const unsigned* pl = &As[r * RS + ks * 8 + lp];
                const unsigned* ph = &As[(r + 8) * RS + ks * 8 + lp];
                a0[mt] = pl[0]; a2[mt] = pl[4];
                a1[mt] = ph[0]; a3[mt] = ph[4];
            }
            unsigned b0[NT], b1[NT];
#pragma unroll
            for (int nt = 0; nt < NT; nt++) {
                const unsigned* pb = &Bs[(wn * WCOLS + nt * 8 + lq) * RS + ks * 8 + lp];
                b0[nt] = pb[0]; b1[nt] = pb[4];
            }
#pragma unroll
            for (int mt = 0; mt < MT; mt++)
#pragma unroll
                for (int nt = 0; nt < NT; nt++)
                    asm volatile(
                        "mma.sync.aligned.m16n8k16.row.col.f32.f16.f16.f32 "
                        "{%0,%1,%2,%3}, {%4,%5,%6,%7}, {%8,%9}, {%0,%1,%2,%3};"
                        : "+f"(acc[mt][nt][0]), "+f"(acc[mt][nt][1]),
                          "+f"(acc[mt][nt][2]), "+f"(acc[mt][nt][3])
                        : "r"(a0[mt]), "r"(a1[mt]), "r"(a2[mt]), "r"(a3[mt]),
                          "r"(b0[nt]), "r"(b1[nt]));
        }
        __syncthreads();
    }

    float ps[2][MT], pd[2][MT];
#pragma unroll
    for (int mt = 0; mt < MT; mt++) { ps[0][mt]=ps[1][mt]=pd[0][mt]=pd[1][mt]=0.f; }
#pragma unroll
    for (int mt = 0; mt < MT; mt++) {
        int r = m0 + wm * 64 + mt * 16 + lq;
#pragma unroll
        for (int nt = 0; nt < NT; nt++) {
            int c = n0 + wn * WCOLS + nt * 8 + 2 * lp;
            float s0 = avs[c], s1 = avs[c + 1];
            float d0 = avd[c], d1 = avd[c + 1];
            float* a = acc[mt][nt];
            if (r < M)     st2(C + (size_t)r * N + c,       a[0], a[1]);
            if (r + 8 < M) st2(C + (size_t)(r + 8) * N + c, a[2], a[3]);
            ps[0][mt] += a[0]*s0 + a[1]*s1;  ps[1][mt] += a[2]*s0 + a[3]*s1;
            pd[0][mt] += a[0]*d0 + a[1]*d1;  pd[1][mt] += a[2]*d0 + a[3]*d1;
        }
    }
#pragma unroll
    for (int o = 1; o <= 2; o <<= 1)
#pragma unroll
        for (int mt = 0; mt < MT; mt++) {
            ps[0][mt] += __shfl_xor_sync(0xffffffffu, ps[0][mt], o);
            ps[1][mt] += __shfl_xor_sync(0xffffffffu, ps[1][mt], o);
            pd[0][mt] += __shfl_xor_sync(0xffffffffu, pd[0][mt], o);
            pd[1][mt] += __shfl_xor_sync(0xffffffffu, pd[1][mt], o);
        }
    if (lp == 0) {
        int head = (n0 + wn * WCOLS) / 64;
#pragma unroll
        for (int mt = 0; mt < MT; mt++) {
            int r = m0 + wm * 64 + mt * 16 + lq;
            if (r < M) {
                atomicAdd(&as_out[r * H + head], ps[0][mt]);
                atomicAdd(&ad_out[r * H + head], pd[0][mt]);
            }
            if (r + 8 < M) {
                atomicAdd(&as_out[(r + 8) * H + head], ps[1][mt]);
                atomicAdd(&ad_out[(r + 8) * H + head], pd[1][mt]);
            }
        }
    }
}

// ---------------- GAT layer 1 aggregation ----------------
// 2 warps per node, each owns 256 cols; lane owns 8 fp16 cols (one LDG.128/edge).
// Full distance-1 prefetch of (w, feature).
__global__ __launch_bounds__(256) void gat1_k(
    const __half* __restrict__ feat, const float* __restrict__ w1,
    const float* __restrict__ bias, __half* __restrict__ out, int N)
{
    int warp = threadIdx.x >> 5, lane = threadIdx.x & 31;
    int node = blockIdx.x * 4 + (warp >> 1);
    int halfid = warp & 1;
    if (node >= N) return;
    int beg = g_off[node], end = g_off[node + 1];

    int col0 = halfid * 256 + lane * 8;
    int myh  = col0 >> 6;
    const __half* fb = feat + col0;

    float acc[8] = {0,0,0,0,0,0,0,0};
    float wsum = 0.f;

    float cw[4]; uint4 cf[4];
#pragma unroll
    for (int u = 0; u < 4; u++) {
        int e = beg + u; bool ok = e < end; e = ok ? e : end - 1;
        int s = g_csr[e];
        cw[u] = ok ? w1[e * 8 + myh] : 0.f;
        cf[u] = *(const uint4*)(fb + (size_t)s * D1);
    }
    for (int i = beg; i < end; i += 4) {
        float nw[4] = {0,0,0,0}; uint4 nf[4];
        int nb = i + 4;
        if (nb < end) {
#pragma unroll
            for (int u = 0; u < 4; u++) {
                int e = nb + u; bool ok = e < end; e = ok ? e : end - 1;
                int s = g_csr[e];
                nw[u] = ok ? w1[e * 8 + myh] : 0.f;
                nf[u] = *(const uint4*)(fb + (size_t)s * D1);
            }
        } else {
#pragma unroll
            for (int u = 0; u < 4; u++) nf[u] = make_uint4(0,0,0,0);
        }
#pragma unroll
        for (int u = 0; u < 4; u++) {
            float w = cw[u];
            wsum += w;
            float2 f0 = __half22float2(*reinterpret_cast<__half2*>(&cf[u].x));
            float2 f1 = __half22float2(*reinterpret_cast<__half2*>(&cf[u].y));
            float2 f2 = __half22float2(*reinterpret_cast<__half2*>(&cf[u].z));
            float2 f3 = __half22float2(*reinterpret_cast<__half2*>(&cf[u].w));
            acc[0] += w * f0.x; acc[1] += w * f0.y;
            acc[2] += w * f1.x; acc[3] += w * f1.y;
            acc[4] += w * f2.x; acc[5] += w * f2.y;
            acc[6] += w * f3.x; acc[7] += w * f3.y;
        }
#pragma unroll
        for (int u = 0; u < 4; u++) { cw[u] = nw[u]; cf[u] = nf[u]; }
    }
    float inv = 1.f / wsum;
    const float4* bp = (const float4*)(bias + col0);
    float4 b0 = bp[0], b1 = bp[1];
    h2x4 pack;
    pack.a = __floats2half2_rn(fmaxf(acc[0]*inv + b0.x, 0.f), fmaxf(acc[1]*inv + b0.y, 0.f));
    pack.b = __floats2half2_rn(fmaxf(acc[2]*inv + b0.z, 0.f), fmaxf(acc[3]*inv + b0.w, 0.f));
    pack.c = __floats2half2_rn(fmaxf(acc[4]*inv + b1.x, 0.f), fmaxf(acc[5]*inv + b1.y, 0.f));
    pack.d = __floats2half2_rn(fmaxf(acc[6]*inv + b1.z, 0.f), fmaxf(acc[7]*inv + b1.w, 0.f));
    *(h2x4*)(out + (size_t)node * D1 + col0) = pack;
}

// ---------------- GAT layer 2 (weights computed inline) + ReLU + pool ----------
// one warp per node; lane owns 2 fp16 cols. Per-edge weight exp(leaky(as2[s]+ad2[d]))
// computed from a prefetched as2 gather; padded slots use -inf -> w = 0.
__global__ __launch_bounds__(256) void gat2_k(
    const __half* __restrict__ feat, const float* __restrict__ as_,
    const float* __restrict__ ad_, const float* __restrict__ bias,
    const int* __restrict__ batch, int N)
{
    int warp = threadIdx.x >> 5, lane = threadIdx.x & 31;
    int node = blockIdx.x * 8 + warp;
    if (node >= N) return;
    int beg = g_off[node], end = g_off[node + 1];
    float adl = ad_[node];

    float2 acc = make_float2(0.f, 0.f);
    float wsum = 0.f;
    const __half* fb = feat + lane * 2;
    const float NEG_INF = -__int_as_float(0x7f800000);

    float ca[4]; __half2 cf[4];
#pragma unroll
    for (int u = 0; u < 4; u++) {
        int e = beg + u; bool ok = e < end; e = ok ? e : end - 1;
        int s = g_csr[e];
        ca[u] = ok ? as_[s] : NEG_INF;
        cf[u] = *(const __half2*)(fb + (size_t)s * HID);
    }
    for (int i = beg; i < end; i += 4) {
        float na[4]; __half2 nf[4];
        int nb = i + 4;
        if (nb < end) {
#pragma unroll
            for (int u = 0; u < 4; u++) {
                int e = nb + u; bool ok = e < end; e = ok ? e : end - 1;
                int s = g_csr[e];
                na[u] = ok ? as_[s] : NEG_INF;
                nf[u] = *(const __half2*)(fb + (size_t)s * HID);
            }
        } else {
#pragma unroll
            for (int u = 0; u < 4; u++) { na[u] = NEG_INF; nf[u] = __floats2half2_rn(0.f, 0.f); }
        }
#pragma unroll
        for (int u = 0; u < 4; u++) {
            float v = ca[u] + adl;
            v = v > 0.f ? v : NEG_SLOPE * v;
            float w = __expf(v);
            wsum += w;
            float2 f = __half22float2(cf[u]);
            acc.x += w * f.x;
            acc.y += w * f.y;
        }
#pragma unroll
        for (int u = 0; u < 4; u++) { ca[u] = na[u]; cf[u] = nf[u]; }
    }
    float inv = 1.f / wsum;
    int col = lane * 2;
    float v0 = fmaxf(acc.x * inv + bias[col],     0.f);
    float v1 = fmaxf(acc.y * inv + bias[col + 1], 0.f);
    int g = batch[node];
    atomicAdd(&g_pool[g * HID + col],     v0);
    atomicAdd(&g_pool[g * HID + col + 1], v1);
}

// ---------------- FC ----------------
__global__ void fc_k(const float* __restrict__ W, const float* __restrict__ b,
                     float* __restrict__ out)
{
    int t = threadIdx.x;
    if (t >= N_GRAPHS * 10) return;
    int g = t / 10, o = t % 10;
    float s = b[o];
#pragma unroll
    for (int c = 0; c < HID; c++) s += g_pool[g * HID + c] * W[c * 10 + o];
    out[t] = s;
}

// ---------------- host ----------------
extern "C" void kernel_launch(void* const* d_in, const int* in_sizes, int n_in,
                              void* d_out, int out_size)
{
    const float* x      = (const float*)d_in[0];
    const int*   ei     = (const int*)  d_in[1];
    const int*   batch  = (const int*)  d_in[2];
    const float* W1     = (const float*)d_in[3];
    const float* a_src1 = (const float*)d_in[4];
    const float* a_dst1 = (const float*)d_in[5];
    const float* b1     = (const float*)d_in[6];
    const float* W2     = (const float*)d_in[7];
    const float* a_src2 = (const float*)d_in[8];
    const float* a_dst2 = (const float*)d_in[9];
    const float* b2     = (const float*)d_in[10];
    const float* W_fc   = (const float*)d_in[11];
    const float* b_fc   = (const float*)d_in[12];

    int N = in_sizes[0] / IN_DIM;      // 50000
    int E = in_sizes[1] / 2;           // 800000
    int ET = E + N;

    __half *h1, *o1, *h2;
    float *as1, *ad1, *as2, *ad2, *w1b;
    cudaGetSymbolAddress((void**)&h1,  g_h1);
    cudaGetSymbolAddress((void**)&o1,  g_o1);
    cudaGetSymbolAddress((void**)&h2,  g_h2);
    cudaGetSymbolAddress((void**)&as1, g_as1);
    cudaGetSymbolAddress((void**)&ad1, g_ad1);
    cudaGetSymbolAddress((void**)&as2, g_as2);
    cudaGetSymbolAddress((void**)&ad2, g_ad2);
    cudaGetSymbolAddress((void**)&w1b, g_w1);

    // side stream + events for fork-join (created once; identical work per call)
    static cudaStream_t s1 = 0;
    static cudaEvent_t evF = 0, evJ = 0;
    if (!s1) {
        cudaStreamCreate(&s1);
        cudaEventCreateWithFlags(&evF, cudaEventDisableTiming);
        cudaEventCreateWithFlags(&evJ, cudaEventDisableTiming);
    }

    // 1: zero (both branches depend on it)
    zero_k<<<(N * H1 + 255) / 256, 256>>>(N);
    cudaEventRecord(evF, 0);
    cudaStreamWaitEvent(s1, evF, 0);

    // branch B (s1): CSR build — overlaps GEMM1 on the default stream
    hist_k<<<(E + 255) / 256, 256, 0, s1>>>(ei, E);
    scan_k<<<1, 1024, 0, s1>>>(N);
    // branch A (default): fp16 GEMM1 + alpha epilogue (4th launch = profiled slot)
    mma_ep<128, H1><<<dim3((N + 127) / 128, D1 / 128), 256>>>(
        x, W1, h1, a_src1, a_dst1, as1, ad1, N, D1, IN_DIM);
    scatter_self_k<<<(E + N + 255) / 256, 256, 0, s1>>>(ei, E, N);
    cudaEventRecord(evJ, s1);
    cudaStreamWaitEvent(0, evJ, 0);    // join: wk1 needs CSR + as1/ad1

    // edge weights layer 1
    wk1_k<<<(ET * H1 + 255) / 256, 256>>>(ET);
    // GAT layer 1 aggregation
    gat1_k<<<(N + 3) / 4, 256>>>(h1, w1b, b1, o1, N);
    // fp16 GEMM2 + alpha epilogue (A fp16)
    mma_ep<64, 1><<<dim3((N + 127) / 128, 1), 256>>>(
        o1, W2, h2, a_src2, a_dst2, as2, ad2, N, HID, D1);
    // GAT layer 2 (inline weights) + ReLU + pool
    gat2_k<<<(N + 7) / 8, 256>>>(h2, as2, ad2, b2, batch, N);
    // FC
    fc_k<<<1, 640>>>(W_fc, b_fc, (float*)d_out);
}

// round 11
// speedup vs baseline: 1.0917x; 1.0673x over previous
#include <cuda_runtime.h>
#include <cuda_fp16.h>
#include <math.h>

#define N_NODES   50000
#define N_GRAPHS  64
#define IN_DIM    128
#define HID       64
#define H1        8
#define D1        (H1*HID)          /* 512 */
#define E_MAX     800000
#define ET_MAX    (E_MAX + N_NODES) /* edges + self loops */
#define NEG_SLOPE 0.2f

// ---------------- scratch (static device arrays; no allocation) ----------------
__device__ __half g_h1 [N_NODES * D1];    // x @ W1 (fp16)
__device__ __half g_o1 [N_NODES * D1];    // relu(gat1) (fp16)
__device__ __half g_h2 [N_NODES * HID];   // o1 @ W2 (fp16)
__device__ float g_as1[N_NODES * H1];     // [node][head]
__device__ float g_ad1[N_NODES * H1];
__device__ float g_as2[N_NODES];
__device__ float g_ad2[N_NODES];
__device__ int   g_csr[ET_MAX];           // src ids grouped by dst
__device__ int   g_off[N_NODES + 1];
__device__ int   g_cnt[N_NODES];          // histogram, then scatter cursor
__device__ float g_pool[N_GRAPHS * HID];

struct h2x4 { __half2 a, b, c, d; };      // 16-byte fp16 vector store

// ---------------- zero all accumulators ----------------
__global__ void zero_k(int N) {
    int i = blockIdx.x * blockDim.x + threadIdx.x;
    if (i < N * H1) { g_as1[i] = 0.f; g_ad1[i] = 0.f; }
    if (i < N)      { g_cnt[i] = 0;   g_as2[i] = 0.f; g_ad2[i] = 0.f; }
    if (i < N_GRAPHS * HID) g_pool[i] = 0.f;
}

__global__ void hist_k(const int* __restrict__ ei, int E) {
    int i = blockIdx.x * blockDim.x + threadIdx.x;
    if (i < E) atomicAdd(&g_cnt[ei[E + i]], 1);   // dst
}

// single-block scan of (cnt[i] + 1) -> exclusive offsets; also seeds cursor
__global__ void scan_k(int n) {
    __shared__ int part[1024];
    int t = threadIdx.x;
    int ch = (n + 1023) / 1024;
    int b = t * ch, e = min(b + ch, n);
    int s = 0;
    for (int i = b; i < e; i++) s += g_cnt[i] + 1;
    part[t] = s;
    __syncthreads();
    for (int off = 1; off < 1024; off <<= 1) {
        int v = (t >= off) ? part[t - off] : 0;
        __syncthreads();
        part[t] += v;
        __syncthreads();
    }
    int base = (t == 0) ? 0 : part[t - 1];
    for (int i = b; i < e; i++) {
        int c = g_cnt[i];
        g_off[i] = base;
        g_cnt[i] = base;          // cursor for scatter
        base += c + 1;            // +1 reserves self-loop slot
    }
    if (t == 1023) g_off[n] = part[1023];
}

// scatter edges + fill reserved self-loop slots
__global__ void scatter_self_k(const int* __restrict__ ei, int E, int N) {
    int i = blockIdx.x * blockDim.x + threadIdx.x;
    if (i < E) {
        int s = ei[i], d = ei[E + i];
        g_csr[atomicAdd(&g_cnt[d], 1)] = s;
    } else {
        int n = i - E;
        if (n < N) g_csr[g_off[n + 1] - 1] = n;
    }
}

// ---------------- fp16 tensor-core GEMM + fused alpha epilogue ----------------
__device__ __forceinline__ unsigned pkh2(float a, float b) {
    __half2 h = __floats2half2_rn(a, b);
    return *reinterpret_cast<unsigned*>(&h);
}
__device__ __forceinline__ void ldA16(const float* p, uint4& x, uint4& y) {
    float4 f0 = *(const float4*)p,       f1 = *(const float4*)(p + 4);
    float4 f2 = *(const float4*)(p + 8), f3 = *(const float4*)(p + 12);
    x = make_uint4(pkh2(f0.x, f0.y), pkh2(f0.z, f0.w), pkh2(f1.x, f1.y), pkh2(f1.z, f1.w));
    y = make_uint4(pkh2(f2.x, f2.y), pkh2(f2.z, f2.w), pkh2(f3.x, f3.y), pkh2(f3.z, f3.w));
}
__device__ __forceinline__ void ldA16(const __half* p, uint4& x, uint4& y) {
    x = *(const uint4*)p;
    y = *(const uint4*)(p + 8);
}
__device__ __forceinline__ void st2(float* p, float a, float b) {
    *(float2*)p = make_float2(a, b);
}
__device__ __forceinline__ void st2(__half* p, float a, float b) {
    *(__half2*)p = __floats2half2_rn(a, b);
}

// C[M,N] = A[M,K] x B[K,N] via mma.sync m16n8k16 fp16, fp32 accumulate.
// Register-double-buffered staging; fragments via ldmatrix.x4 (A: one per mt,
// B: two n8 groups per instruction). Fused alpha epilogue (atomicAdd partials).
template<int BN, int H, typename TA, typename TC>
__global__ __launch_bounds__(256, 2) void mma_ep(
    const TA* __restrict__ A, const float* __restrict__ B, TC* __restrict__ C,
    const float* __restrict__ avs, const float* __restrict__ avd,
    float* __restrict__ as_out, float* __restrict__ ad_out,
    int M, int N, int K)
{
    constexpr int BM = 128, BK = 32;
    constexpr int MT = 4, NT = BN / 32;   // warp tile: 64 x (BN/4)
    constexpr int WCOLS = BN / 4;
    constexpr int RS = 20;                // u32 words per row (16 data + 4 pad)
    constexpr int KE = BK * BN / 256;     // B k-elements per thread (16 or 8)
    __shared__ unsigned As[BM * RS];      // [row][k/2] half2 words
    __shared__ unsigned Bs[BN * RS];      // [n][k/2]   half2 words

    int t = threadIdx.x, lane = t & 31;
    int wid = t >> 5, wm = wid >> 2, wn = wid & 3;
    int lq = lane >> 2, lp = lane & 3;
    int m0 = blockIdx.x * BM, n0 = blockIdx.y * BN;

    float acc[MT][NT][4];
#pragma unroll
    for (int mt = 0; mt < MT; mt++)
#pragma unroll
        for (int nt = 0; nt < NT; nt++)
#pragma unroll
            for (int v = 0; v < 4; v++) acc[mt][nt][v] = 0.f;

    int ar = t >> 1, acb = (t & 1) * 16;
    bool aok = (m0 + ar) < M;
    const TA* Ap = A + (size_t)(m0 + ar) * K + acb;
    int bn = t % BN, bkb = (t / BN) * KE;
    const float* Bp = B + n0 + bn;

    // ldmatrix per-lane byte offsets
    unsigned asb = (unsigned)__cvta_generic_to_shared(As);
    unsigned bsb = (unsigned)__cvta_generic_to_shared(Bs);
    unsigned laneA = ((lane & 7) + ((lane >> 3) & 1) * 8) * RS * 4 + ((lane >> 4) & 1) * 16;
    unsigned laneB = ((lane & 7) + ((lane >> 4) & 1) * 8) * RS * 4 + ((lane >> 3) & 1) * 16;

    uint4 ax = make_uint4(0,0,0,0), ay = make_uint4(0,0,0,0);
    unsigned bt[KE / 2];
    if (aok) ldA16(Ap, ax, ay);
#pragma unroll
    for (int j = 0; j < KE / 2; j++) {
        float v0 = Bp[(size_t)(bkb + 2 * j) * N];
        float v1 = Bp[(size_t)(bkb + 2 * j + 1) * N];
        bt[j] = pkh2(v0, v1);
    }

    for (int k0 = 0; k0 < K; k0 += BK) {
        uint4* adst = (uint4*)&As[ar * RS + (acb >> 1)];
        adst[0] = ax; adst[1] = ay;
        uint4* bdst = (uint4*)&Bs[bn * RS + (bkb >> 1)];
#pragma unroll
        for (int j = 0; j < KE / 2; j += 4)
            bdst[j >> 2] = make_uint4(bt[j], bt[j+1], bt[j+2], bt[j+3]);
        __syncthreads();
        int kn = k0 + BK;
        if (kn < K) {
            ax = make_uint4(0,0,0,0); ay = make_uint4(0,0,0,0);
            if (aok) ldA16(Ap + kn, ax, ay);
#pragma unroll
            for (int j = 0; j < KE / 2; j++) {
                float v0 = Bp[(size_t)(kn + bkb + 2 * j) * N];
                float v1 = Bp[(size_t)(kn + bkb + 2 * j + 1) * N];
                bt[j] = pkh2(v0, v1);
            }
        }
#pragma unroll
        for (int ks = 0; ks < BK / 16; ks++) {
            unsigned a0[MT], a1[MT], a2[MT], a3[MT];
#pragma unroll
            for (int mt = 0; mt < MT; mt++) {
                unsigned addr = asb + ((wm * 64 + mt * 16) * RS + ks * 8) * 4 + laneA;
                asm volatile("ldmatrix.sync.aligned.m8n8.x4.shared.b16 {%0,%1,%2,%3}, [%4];"
                    : "=r"(a0[mt]), "=r"(a1[mt]), "=r"(a2[mt]), "=r"(a3[mt]) : "r"(addr));
            }
            unsigned b0[NT], b1[NT];
#pragma unroll
            for (int np = 0; np < NT / 2; np++) {
                unsigned addr = bsb + ((wn * WCOLS + np * 16) * RS + ks * 8) * 4 + laneB;
                asm volatile("ldmatrix.sync.aligned.m8n8.x4.shared.b16 {%0,%1,%2,%3}, [%4];"
                    : "=r"(b0[2*np]), "=r"(b1[2*np]), "=r"(b0[2*np+1]), "=r"(b1[2*np+1]) : "r"(addr));
            }
#pragma unroll
            for (int mt = 0; mt < MT; mt++)
#pragma unroll
                for (int nt = 0; nt < NT; nt++)
                    asm volatile(
                        "mma.sync.aligned.m16n8k16.row.col.f32.f16.f16.f32 "
                        "{%0,%1,%2,%3}, {%4,%5,%6,%7}, {%8,%9}, {%0,%1,%2,%3};"
                        : "+f"(acc[mt][nt][0]), "+f"(acc[mt][nt][1]),
                          "+f"(acc[mt][nt][2]), "+f"(acc[mt][nt][3])
                        : "r"(a0[mt]), "r"(a1[mt]), "r"(a2[mt]), "r"(a3[mt]),
                          "r"(b0[nt]), "r"(b1[nt]));
        }
        __syncthreads();
    }

    float ps[2][MT], pd[2][MT];
#pragma unroll
    for (int mt = 0; mt < MT; mt++) { ps[0][mt]=ps[1][mt]=pd[0][mt]=pd[1][mt]=0.f; }
#pragma unroll
    for (int mt = 0; mt < MT; mt++) {
        int r = m0 + wm * 64 + mt * 16 + lq;
#pragma unroll
        for (int nt = 0; nt < NT; nt++) {
            int c = n0 + wn * WCOLS + nt * 8 + 2 * lp;
            float s0 = avs[c], s1 = avs[c + 1];
            float d0 = avd[c], d1 = avd[c + 1];
            float* a = acc[mt][nt];
            if (r < M)     st2(C + (size_t)r * N + c,       a[0], a[1]);
            if (r + 8 < M) st2(C + (size_t)(r + 8) * N + c, a[2], a[3]);
            ps[0][mt] += a[0]*s0 + a[1]*s1;  ps[1][mt] += a[2]*s0 + a[3]*s1;
            pd[0][mt] += a[0]*d0 + a[1]*d1;  pd[1][mt] += a[2]*d0 + a[3]*d1;
        }
    }
#pragma unroll
    for (int o = 1; o <= 2; o <<= 1)
#pragma unroll
        for (int mt = 0; mt < MT; mt++) {
            ps[0][mt] += __shfl_xor_sync(0xffffffffu, ps[0][mt], o);
            ps[1][mt] += __shfl_xor_sync(0xffffffffu, ps[1][mt], o);
            pd[0][mt] += __shfl_xor_sync(0xffffffffu, pd[0][mt], o);
            pd[1][mt] += __shfl_xor_sync(0xffffffffu, pd[1][mt], o);
        }
    if (lp == 0) {
        int head = (n0 + wn * WCOLS) / 64;
#pragma unroll
        for (int mt = 0; mt < MT; mt++) {
            int r = m0 + wm * 64 + mt * 16 + lq;
            if (r < M) {
                atomicAdd(&as_out[r * H + head], ps[0][mt]);
                atomicAdd(&ad_out[r * H + head], pd[0][mt]);
            }
            if (r + 8 < M) {
                atomicAdd(&as_out[(r + 8) * H + head], ps[1][mt]);
                atomicAdd(&ad_out[(r + 8) * H + head], pd[1][mt]);
            }
        }
    }
}

// ---------------- GAT layer 1 aggregation (weights computed inline) ----------
// 2 warps per node, each owns 256 cols; lane owns 8 fp16 cols (one LDG.128/edge).
// Per-lane weight: exp(leaky(as1[s*8+myh] + ad1[node*8+myh])); padded slots use
// -inf -> w = 0. Full distance-1 prefetch of (alpha, feature).
__global__ __launch_bounds__(256) void gat1_k(
    const __half* __restrict__ feat, const float* __restrict__ as_,
    const float* __restrict__ ad_, const float* __restrict__ bias,
    __half* __restrict__ out, int N)
{
    int warp = threadIdx.x >> 5, lane = threadIdx.x & 31;
    int node = blockIdx.x * 4 + (warp >> 1);
    int halfid = warp & 1;
    if (node >= N) return;
    int beg = g_off[node], end = g_off[node + 1];

    int col0 = halfid * 256 + lane * 8;
    int myh  = col0 >> 6;
    const __half* fb = feat + col0;
    float adl = ad_[node * 8 + myh];
    const float NEG_INF = -__int_as_float(0x7f800000);

    float acc[8] = {0,0,0,0,0,0,0,0};
    float wsum = 0.f;

    float ca[4]; uint4 cf[4];
#pragma unroll
    for (int u = 0; u < 4; u++) {
        int e = beg + u; bool ok = e < end; e = ok ? e : end - 1;
        int s = g_csr[e];
        ca[u] = ok ? as_[s * 8 + myh] : NEG_INF;
        cf[u] = *(const uint4*)(fb + (size_t)s * D1);
    }
    for (int i = beg; i < end; i += 4) {
        float na[4]; uint4 nf[4];
        int nb = i + 4;
        if (nb < end) {
#pragma unroll
            for (int u = 0; u < 4; u++) {
                int e = nb + u; bool ok = e < end; e = ok ? e : end - 1;
                int s = g_csr[e];
                na[u] = ok ? as_[s * 8 + myh] : NEG_INF;
                nf[u] = *(const uint4*)(fb + (size_t)s * D1);
            }
        } else {
#pragma unroll
            for (int u = 0; u < 4; u++) { na[u] = NEG_INF; nf[u] = make_uint4(0,0,0,0); }
        }
#pragma unroll
        for (int u = 0; u < 4; u++) {
            float v = ca[u] + adl;
            v = v > 0.f ? v : NEG_SLOPE * v;
            float w = __expf(v);
            wsum += w;
            float2 f0 = __half22float2(*reinterpret_cast<__half2*>(&cf[u].x));
            float2 f1 = __half22float2(*reinterpret_cast<__half2*>(&cf[u].y));
            float2 f2 = __half22float2(*reinterpret_cast<__half2*>(&cf[u].z));
            float2 f3 = __half22float2(*reinterpret_cast<__half2*>(&cf[u].w));
            acc[0] += w * f0.x; acc[1] += w * f0.y;
            acc[2] += w * f1.x; acc[3] += w * f1.y;
            acc[4] += w * f2.x; acc[5] += w * f2.y;
            acc[6] += w * f3.x; acc[7] += w * f3.y;
        }
#pragma unroll
        for (int u = 0; u < 4; u++) { ca[u] = na[u]; cf[u] = nf[u]; }
    }
    float inv = 1.f / wsum;
    const float4* bp = (const float4*)(bias + col0);
    float4 b0 = bp[0], b1 = bp[1];
    h2x4 pack;
    pack.a = __floats2half2_rn(fmaxf(acc[0]*inv + b0.x, 0.f), fmaxf(acc[1]*inv + b0.y, 0.f));
    pack.b = __floats2half2_rn(fmaxf(acc[2]*inv + b0.z, 0.f), fmaxf(acc[3]*inv + b0.w, 0.f));
    pack.c = __floats2half2_rn(fmaxf(acc[4]*inv + b1.x, 0.f), fmaxf(acc[5]*inv + b1.y, 0.f));
    pack.d = __floats2half2_rn(fmaxf(acc[6]*inv + b1.z, 0.f), fmaxf(acc[7]*inv + b1.w, 0.f));
    *(h2x4*)(out + (size_t)node * D1 + col0) = pack;
}

// ---------------- GAT layer 2 (weights inline) + ReLU + global_add_pool -------
__global__ __launch_bounds__(256) void gat2_k(
    const __half* __restrict__ feat, const float* __restrict__ as_,
    const float* __restrict__ ad_, const float* __restrict__ bias,
    const int* __restrict__ batch, int N)
{
    int warp = threadIdx.x >> 5, lane = threadIdx.x & 31;
    int node = blockIdx.x * 8 + warp;
    if (node >= N) return;
    int beg = g_off[node], end = g_off[node + 1];
    float adl = ad_[node];

    float2 acc = make_float2(0.f, 0.f);
    float wsum = 0.f;
    const __half* fb = feat + lane * 2;
    const float NEG_INF = -__int_as_float(0x7f800000);

    float ca[4]; __half2 cf[4];
#pragma unroll
    for (int u = 0; u < 4; u++) {
        int e = beg + u; bool ok = e < end; e = ok ? e : end - 1;
        int s = g_csr[e];
        ca[u] = ok ? as_[s] : NEG_INF;
        cf[u] = *(const __half2*)(fb + (size_t)s * HID);
    }
    for (int i = beg; i < end; i += 4) {
        float na[4]; __half2 nf[4];
        int nb = i + 4;
        if (nb < end) {
#pragma unroll
            for (int u = 0; u < 4; u++) {
                int e = nb + u; bool ok = e < end; e = ok ? e : end - 1;
                int s = g_csr[e];
                na[u] = ok ? as_[s] : NEG_INF;
                nf[u] = *(const __half2*)(fb + (size_t)s * HID);
            }
        } else {
#pragma unroll
            for (int u = 0; u < 4; u++) { na[u] = NEG_INF; nf[u] = __floats2half2_rn(0.f, 0.f); }
        }
#pragma unroll
        for (int u = 0; u < 4; u++) {
            float v = ca[u] + adl;
            v = v > 0.f ? v : NEG_SLOPE * v;
            float w = __expf(v);
            wsum += w;
            float2 f = __half22float2(cf[u]);
            acc.x += w * f.x;
            acc.y += w * f.y;
        }
#pragma unroll
        for (int u = 0; u < 4; u++) { ca[u] = na[u]; cf[u] = nf[u]; }
    }
    float inv = 1.f / wsum;
    int col = lane * 2;
    float v0 = fmaxf(acc.x * inv + bias[col],     0.f);
    float v1 = fmaxf(acc.y * inv + bias[col + 1], 0.f);
    int g = batch[node];
    atomicAdd(&g_pool[g * HID + col],     v0);
    atomicAdd(&g_pool[g * HID + col + 1], v1);
}

// ---------------- FC ----------------
__global__ void fc_k(const float* __restrict__ W, const float* __restrict__ b,
                     float* __restrict__ out)
{
    int t = threadIdx.x;
    if (t >= N_GRAPHS * 10) return;
    int g = t / 10, o = t % 10;
    float s = b[o];
#pragma unroll
    for (int c = 0; c < HID; c++) s += g_pool[g * HID + c] * W[c * 10 + o];
    out[t] = s;
}

// ---------------- host ----------------
extern "C" void kernel_launch(void* const* d_in, const int* in_sizes, int n_in,
                              void* d_out, int out_size)
{
    const float* x      = (const float*)d_in[0];
    const int*   ei     = (const int*)  d_in[1];
    const int*   batch  = (const int*)  d_in[2];
    const float* W1     = (const float*)d_in[3];
    const float* a_src1 = (const float*)d_in[4];
    const float* a_dst1 = (const float*)d_in[5];
    const float* b1     = (const float*)d_in[6];
    const float* W2     = (const float*)d_in[7];
    const float* a_src2 = (const float*)d_in[8];
    const float* a_dst2 = (const float*)d_in[9];
    const float* b2     = (const float*)d_in[10];
    const float* W_fc   = (const float*)d_in[11];
    const float* b_fc   = (const float*)d_in[12];

    int N = in_sizes[0] / IN_DIM;      // 50000
    int E = in_sizes[1] / 2;           // 800000

    __half *h1, *o1, *h2;
    float *as1, *ad1, *as2, *ad2;
    cudaGetSymbolAddress((void**)&h1,  g_h1);
    cudaGetSymbolAddress((void**)&o1,  g_o1);
    cudaGetSymbolAddress((void**)&h2,  g_h2);
    cudaGetSymbolAddress((void**)&as1, g_as1);
    cudaGetSymbolAddress((void**)&ad1, g_ad1);
    cudaGetSymbolAddress((void**)&as2, g_as2);
    cudaGetSymbolAddress((void**)&ad2, g_ad2);

    // side stream + events for fork-join (created once; identical work per call)
    static cudaStream_t s1 = 0;
    static cudaEvent_t evF = 0, evJ = 0;
    if (!s1) {
        cudaStreamCreate(&s1);
        cudaEventCreateWithFlags(&evF, cudaEventDisableTiming);
        cudaEventCreateWithFlags(&evJ, cudaEventDisableTiming);
    }

    // 1: zero (both branches depend on it)
    zero_k<<<(N * H1 + 255) / 256, 256>>>(N);
    cudaEventRecord(evF, 0);
    cudaStreamWaitEvent(s1, evF, 0);

    // branch B (s1): CSR build — overlaps GEMM1 on the default stream
    hist_k<<<(E + 255) / 256, 256, 0, s1>>>(ei, E);
    scan_k<<<1, 1024, 0, s1>>>(N);
    // branch A (default): fp16 GEMM1 + alpha epilogue
    mma_ep<128, H1><<<dim3((N + 127) / 128, D1 / 128), 256>>>(
        x, W1, h1, a_src1, a_dst1, as1, ad1, N, D1, IN_DIM);
    scatter_self_k<<<(E + N + 255) / 256, 256, 0, s1>>>(ei, E, N);
    cudaEventRecord(evJ, s1);
    cudaStreamWaitEvent(0, evJ, 0);    // join: gat1 needs CSR + h1 + as1/ad1

    // GAT layer 1 aggregation (6th launch = profiled slot with -s 5)
    gat1_k<<<(N + 3) / 4, 256>>>(h1, as1, ad1, b1, o1, N);
    // fp16 GEMM2 + alpha epilogue (A fp16)
    mma_ep<64, 1><<<dim3((N + 127) / 128, 1), 256>>>(
        o1, W2, h2, a_src2, a_dst2, as2, ad2, N, HID, D1);
    // GAT layer 2 (inline weights) + ReLU + pool
    gat2_k<<<(N + 7) / 8, 256>>>(h2, as2, ad2, b2, batch, N);
    // FC
    fc_k<<<1, 640>>>(W_fc, b_fc, (float*)d_out);
}